// round 1
// baseline (speedup 1.0000x reference)
#include <cuda_runtime.h>
#include <math.h>

#define NB 8
#define LQ 2048
#define CC 256
#define MM 8
#define LL 4
#define PP 4
#define DH 32
#define S_TOTAL 3840
#define MLP 128   // M*L*P
#define LP 16     // L*P

// ---------------- scratch (no allocs allowed) ----------------
__device__ float g_value[NB * S_TOTAL * CC];   // 31.5 MB
__device__ float g_off[NB * LQ * MLP];         // 8.4 MB
__device__ float g_logits[NB * LQ * MLP];      // 8.4 MB
__device__ float g_mixed[NB * LQ * CC];        // 16.8 MB

// ---------------- fp32 tiled GEMM + bias: C = A(MdimxK) @ B(KxNdim) + bias ----------------
// K fixed = 256. BM=BN=64, BK=16, 256 threads, 4x4 per thread.
__global__ void __launch_bounds__(256) gemm_bias_kernel(
    const float* __restrict__ A, const float* __restrict__ B,
    const float* __restrict__ bias, float* __restrict__ Cmat,
    int Mdim, int Ndim)
{
    const int K = 256;
    __shared__ float As[16][65];
    __shared__ float Bs[16][68];

    int tid = threadIdx.x;
    int tx = tid & 15;          // 0..15 -> col group
    int ty = tid >> 4;          // 0..15 -> row group
    int rowBase = blockIdx.x * 64;
    int colBase = blockIdx.y * 64;

    // load mapping
    int arow = tid >> 2;              // 0..63
    int acol = (tid & 3) << 2;        // 0,4,8,12
    int brow = tid >> 4;              // 0..15
    int bcol = (tid & 15) << 2;       // 0..60

    const float* Aptr = A + (size_t)(rowBase + arow) * K + acol;
    const float* Bptr = B + (size_t)brow * Ndim + colBase + bcol;

    float acc[4][4] = {};

    for (int kt = 0; kt < K; kt += 16) {
        float4 a4 = *(const float4*)(Aptr + kt);
        float4 b4 = *(const float4*)(Bptr + (size_t)kt * Ndim);
        As[acol + 0][arow] = a4.x;
        As[acol + 1][arow] = a4.y;
        As[acol + 2][arow] = a4.z;
        As[acol + 3][arow] = a4.w;
        *(float4*)&Bs[brow][bcol] = b4;
        __syncthreads();

        #pragma unroll
        for (int k = 0; k < 16; k++) {
            float ra[4], rb[4];
            #pragma unroll
            for (int i = 0; i < 4; i++) ra[i] = As[k][ty * 4 + i];
            #pragma unroll
            for (int j = 0; j < 4; j++) rb[j] = Bs[k][tx * 4 + j];
            #pragma unroll
            for (int i = 0; i < 4; i++)
                #pragma unroll
                for (int j = 0; j < 4; j++)
                    acc[i][j] += ra[i] * rb[j];
        }
        __syncthreads();
    }

    int col = colBase + tx * 4;
    float4 bv = *(const float4*)(bias + col);
    #pragma unroll
    for (int i = 0; i < 4; i++) {
        int row = rowBase + ty * 4 + i;
        float4 o;
        o.x = acc[i][0] + bv.x;
        o.y = acc[i][1] + bv.y;
        o.z = acc[i][2] + bv.z;
        o.w = acc[i][3] + bv.w;
        *(float4*)(Cmat + (size_t)row * Ndim + col) = o;
    }
}

// ---------------- prep: loc + softmax(attn) per (n,q,m) ----------------
__global__ void __launch_bounds__(256) prep_kernel(
    const float* __restrict__ rp,      // (N,LQ,L,1)
    float* __restrict__ d_loc,         // (N,LQ,M,L,P)
    float* __restrict__ d_attn)
{
    int idx = blockIdx.x * blockDim.x + threadIdx.x;   // (n*LQ+q)*M + m
    if (idx >= NB * LQ * MM) return;
    int nq = idx / MM;

    const float* off = g_off + (size_t)idx * 0 + (size_t)nq * MLP + (idx % MM) * LP;
    const float* lg  = g_logits + (size_t)nq * MLP + (idx % MM) * LP;

    const float invlen[LL] = {1.0f / 2048.0f, 1.0f / 1024.0f, 1.0f / 512.0f, 1.0f / 256.0f};
    float rpv[LL];
    #pragma unroll
    for (int l = 0; l < LL; l++) rpv[l] = rp[(size_t)nq * LL + l];

    float lgv[LP];
    float mx = -1e30f;
    #pragma unroll
    for (int i = 0; i < LP; i++) { lgv[i] = lg[i]; mx = fmaxf(mx, lgv[i]); }
    float s = 0.f;
    #pragma unroll
    for (int i = 0; i < LP; i++) { lgv[i] = expf(lgv[i] - mx); s += lgv[i]; }
    float inv = 1.0f / s;

    #pragma unroll
    for (int l = 0; l < LL; l++) {
        #pragma unroll
        for (int p = 0; p < PP; p++) {
            int j = l * PP + p;
            d_loc[(size_t)idx * LP + j]  = rpv[l] + off[j] * invlen[l];
            d_attn[(size_t)idx * LP + j] = lgv[j] * inv;
        }
    }
}

// ---------------- deform: one warp per (n,q,m), lane = dh ----------------
__global__ void __launch_bounds__(256) deform_kernel(
    const float* __restrict__ d_loc,
    const float* __restrict__ d_attn)
{
    int gtid = blockIdx.x * blockDim.x + threadIdx.x;
    int warp = gtid >> 5;
    int lane = gtid & 31;
    if (warp >= NB * LQ * MM) return;

    int m  = warp % MM;
    int nq = warp / MM;
    int n  = nq / LQ;

    // lanes 0-15 hold loc[0..15], lanes 16-31 hold attn[0..15]
    float v = (lane < 16) ? d_loc[(size_t)warp * LP + lane]
                          : d_attn[(size_t)warp * LP + (lane - 16)];

    const int   leni[LL]   = {2048, 1024, 512, 256};
    const float lenf[LL]   = {2048.f, 1024.f, 512.f, 256.f};
    const int   starti[LL] = {0, 2048, 3072, 3584};

    float acc = 0.f;
    #pragma unroll
    for (int i = 0; i < LP; i++) {
        float loc = __shfl_sync(0xffffffffu, v, i);
        float aw  = __shfl_sync(0xffffffffu, v, i + 16);
        int l = i >> 2;
        int Ti = leni[l];
        float pos  = loc * lenf[l] - 0.5f;
        float x0f  = floorf(pos);
        float frac = pos - x0f;
        int x0 = (int)x0f;
        float w0 = (x0 >= 0 && x0 < Ti)       ? (1.0f - frac) : 0.0f;
        float w1 = (x0 + 1 >= 0 && x0 + 1 < Ti) ? frac         : 0.0f;
        int i0 = min(max(x0, 0), Ti - 1);
        int i1 = min(max(x0 + 1, 0), Ti - 1);
        const float* base = g_value + ((size_t)(n * S_TOTAL + starti[l]) * MM + m) * DH + lane;
        float v0 = base[(size_t)i0 * MM * DH];
        float v1 = base[(size_t)i1 * MM * DH];
        acc += aw * (w0 * v0 + w1 * v1);
    }

    g_mixed[(size_t)nq * CC + m * DH + lane] = acc;
}

// ---------------- launch ----------------
extern "C" void kernel_launch(void* const* d_in, const int* in_sizes, int n_in,
                              void* d_out, int out_size)
{
    const float* query  = (const float*)d_in[0];
    const float* rp     = (const float*)d_in[1];
    const float* inp    = (const float*)d_in[2];
    // d_in[3] temporal_lens (int64), d_in[4] level_start_index (int64): compile-time constants
    const float* W_off  = (const float*)d_in[5];
    const float* b_off  = (const float*)d_in[6];
    const float* W_attn = (const float*)d_in[7];
    const float* b_attn = (const float*)d_in[8];
    const float* W_val  = (const float*)d_in[9];
    const float* b_val  = (const float*)d_in[10];
    const float* W_out  = (const float*)d_in[11];
    const float* b_out  = (const float*)d_in[12];

    float* out    = (float*)d_out;                       // (N,LQ,C)
    float* o_loc  = out + (size_t)NB * LQ * CC;          // (N,LQ,M,L,P)
    float* o_attn = o_loc + (size_t)NB * LQ * MLP;       // (N,LQ,M,L,P)

    float *value, *offb, *logits, *mixed;
    cudaGetSymbolAddress((void**)&value,  g_value);
    cudaGetSymbolAddress((void**)&offb,   g_off);
    cudaGetSymbolAddress((void**)&logits, g_logits);
    cudaGetSymbolAddress((void**)&mixed,  g_mixed);

    // 1) value projection: (30720 x 256) @ (256 x 256)
    gemm_bias_kernel<<<dim3((NB * S_TOTAL) / 64, CC / 64), 256>>>(inp, W_val, b_val, value, NB * S_TOTAL, CC);
    // 2) offsets + attention logits: (16384 x 256) @ (256 x 128)
    gemm_bias_kernel<<<dim3((NB * LQ) / 64, MLP / 64), 256>>>(query, W_off, b_off, offb, NB * LQ, MLP);
    gemm_bias_kernel<<<dim3((NB * LQ) / 64, MLP / 64), 256>>>(query, W_attn, b_attn, logits, NB * LQ, MLP);
    // 3) loc + softmax into output slices
    prep_kernel<<<(NB * LQ * MM + 255) / 256, 256>>>(rp, o_loc, o_attn);
    // 4) deformable sampling
    deform_kernel<<<(NB * LQ * MM * 32) / 256, 256>>>(o_loc, o_attn);
    // 5) output projection: (16384 x 256) @ (256 x 256)
    gemm_bias_kernel<<<dim3((NB * LQ) / 64, CC / 64), 256>>>(mixed, W_out, b_out, out, NB * LQ, CC);
}

// round 6
// speedup vs baseline: 1.9036x; 1.9036x over previous
#include <cuda_runtime.h>
#include <cuda_bf16.h>
#include <math.h>
#include <stdint.h>

#define NB 8
#define LQ 2048
#define CC 256
#define MM 8
#define LL 4
#define PP 4
#define DH 32
#define S_TOTAL 3840
#define MLP 128
#define LP 16
#define KDIM 256

// ---------------- scratch (no allocs allowed) ----------------
__device__ __align__(16) float g_value[NB * S_TOTAL * CC];
__device__ __align__(16) float g_mixed[NB * LQ * CC];
__device__ __align__(16) __nv_bfloat16 g_inp_hi[NB * S_TOTAL * CC];
__device__ __align__(16) __nv_bfloat16 g_inp_lo[NB * S_TOTAL * CC];
__device__ __align__(16) __nv_bfloat16 g_q_hi[NB * LQ * CC];
__device__ __align__(16) __nv_bfloat16 g_q_lo[NB * LQ * CC];
__device__ __align__(16) __nv_bfloat16 g_mx_hi[NB * LQ * CC];
__device__ __align__(16) __nv_bfloat16 g_mx_lo[NB * LQ * CC];
__device__ __align__(16) __nv_bfloat16 g_wv_hi[CC * KDIM], g_wv_lo[CC * KDIM];
__device__ __align__(16) __nv_bfloat16 g_wo_hi[MLP * KDIM], g_wo_lo[MLP * KDIM];
__device__ __align__(16) __nv_bfloat16 g_wa_hi[MLP * KDIM], g_wa_lo[MLP * KDIM];
__device__ __align__(16) __nv_bfloat16 g_wu_hi[CC * KDIM], g_wu_lo[CC * KDIM];

// ---------------- helpers ----------------
__device__ __forceinline__ uint32_t smem_u32(const void* p) {
    uint32_t a;
    asm("{ .reg .u64 t; cvta.to.shared.u64 t, %1; cvt.u32.u64 %0, t; }" : "=r"(a) : "l"(p));
    return a;
}
static __device__ __forceinline__ uint32_t swz128(uint32_t off) { return off ^ ((off >> 3) & 0x70); }

#define CP_ASYNC16(dst, src) \
    asm volatile("cp.async.cg.shared.global [%0], [%1], 16;" :: "r"(dst), "l"(src))
#define CP_COMMIT() asm volatile("cp.async.commit_group;" ::: "memory")
#define CP_WAIT1() asm volatile("cp.async.wait_group 1;" ::: "memory")
#define CP_WAIT0() asm volatile("cp.async.wait_group 0;" ::: "memory")

#define LDMATRIX_X4(r0, r1, r2, r3, addr) \
    asm volatile("ldmatrix.sync.aligned.m8n8.x4.shared.b16 {%0,%1,%2,%3}, [%4];" \
        : "=r"(r0), "=r"(r1), "=r"(r2), "=r"(r3) : "r"(addr))

#define MMA_BF16(c, a, b) \
    asm volatile("mma.sync.aligned.m16n8k16.row.col.f32.bf16.bf16.f32 " \
        "{%0,%1,%2,%3}, {%4,%5,%6,%7}, {%8,%9}, {%0,%1,%2,%3};" \
        : "+f"((c)[0]), "+f"((c)[1]), "+f"((c)[2]), "+f"((c)[3]) \
        : "r"((a)[0]), "r"((a)[1]), "r"((a)[2]), "r"((a)[3]), "r"((b)[0]), "r"((b)[1]))

// ---------------- weight transpose + split (W[k,n] -> Wt_hi/lo[n,k]) ----------------
__global__ void prep_weights_kernel(
    const float* __restrict__ Wv, const float* __restrict__ Wo,
    const float* __restrict__ Wa, const float* __restrict__ Wu)
{
    int i = blockIdx.x * blockDim.x + threadIdx.x;
    if (i >= 2 * CC * KDIM + 2 * MLP * KDIM) return;
    const float* W; __nv_bfloat16 *H, *Lo; int Nw, j;
    if (i < CC * KDIM)                       { W = Wv; H = g_wv_hi; Lo = g_wv_lo; Nw = CC;  j = i; }
    else if (i < CC * KDIM + MLP * KDIM)     { W = Wo; H = g_wo_hi; Lo = g_wo_lo; Nw = MLP; j = i - CC * KDIM; }
    else if (i < CC * KDIM + 2 * MLP * KDIM) { W = Wa; H = g_wa_hi; Lo = g_wa_lo; Nw = MLP; j = i - CC * KDIM - MLP * KDIM; }
    else                                     { W = Wu; H = g_wu_hi; Lo = g_wu_lo; Nw = CC;  j = i - CC * KDIM - 2 * MLP * KDIM; }
    int k = j & (KDIM - 1);
    int n = j >> 8;
    float x = W[k * Nw + n];
    __nv_bfloat16 h = __float2bfloat16(x);
    H[j] = h;
    Lo[j] = __float2bfloat16(x - __bfloat162float(h));
}

// ---------------- activation split fp32 -> hi/lo bf16 ----------------
__global__ void __launch_bounds__(256) split_kernel(
    const float* __restrict__ x, __nv_bfloat16* __restrict__ hi,
    __nv_bfloat16* __restrict__ lo, int n4)
{
    int i = blockIdx.x * blockDim.x + threadIdx.x;
    if (i >= n4) return;
    float4 v = ((const float4*)x)[i];
    float f[4] = {v.x, v.y, v.z, v.w};
    __nv_bfloat16 h[4], l[4];
#pragma unroll
    for (int t = 0; t < 4; t++) {
        h[t] = __float2bfloat16(f[t]);
        l[t] = __float2bfloat16(f[t] - __bfloat162float(h[t]));
    }
    ((__nv_bfloat162*)hi)[2 * i]     = __nv_bfloat162(h[0], h[1]);
    ((__nv_bfloat162*)hi)[2 * i + 1] = __nv_bfloat162(h[2], h[3]);
    ((__nv_bfloat162*)lo)[2 * i]     = __nv_bfloat162(l[0], l[1]);
    ((__nv_bfloat162*)lo)[2 * i + 1] = __nv_bfloat162(l[2], l[3]);
}

// ---------------- HMMA GEMM: C[row,col] = sum_k A[row,k]*Bt[col,k] (+ bias, epilogues) ----------------
// 3-pass bf16 split: AhBh + AhBl + AlBh.  BM=128 BN=128 BK=64, 8 warps (4m x 2n), 64 acc/thread.
// modes: 0 = bias; 1 = loc epilogue (rp + v*invlen); 2 = softmax over 16-col groups
__global__ void __launch_bounds__(256) gemm_hmma_kernel(
    const __nv_bfloat16* __restrict__ Ahi, const __nv_bfloat16* __restrict__ Alo,
    const __nv_bfloat16* __restrict__ Bhi, const __nv_bfloat16* __restrict__ Blo,
    const float* __restrict__ bias, float* __restrict__ out,
    int Ndim, int mode, const float* __restrict__ rp)
{
    extern __shared__ char smem[];
    uint32_t sb = smem_u32(smem);
    const int tid = threadIdx.x;
    const int lane = tid & 31;
    const int wid = tid >> 5;
    const int warpm = wid & 3;     // 4 warps over M: 32 rows each
    const int warpn = wid >> 2;    // 2 warps over N: 64 cols each
    const int rowBase = blockIdx.x * 128;
    const int colBase = blockIdx.y * 128;

    const int seg = tid & 7;
    const int r0 = tid >> 3;       // 0..31

    float acc[2][8][4];
#pragma unroll
    for (int a = 0; a < 2; a++)
#pragma unroll
        for (int b = 0; b < 8; b++)
#pragma unroll
            for (int c = 0; c < 4; c++) acc[a][b][c] = 0.f;

    // chunk ch in 0..11: pass = ch>>2 (0:hh 1:hl 2:lh), c = ch&3 (k offset 64c)
#define LOAD_CHUNK(ch, buf) do { \
        int _pass = (ch) >> 2, _c = (ch) & 3; \
        const __nv_bfloat16* _Ap = (_pass == 2) ? Alo : Ahi; \
        const __nv_bfloat16* _Bp = (_pass == 1) ? Blo : Bhi; \
        uint32_t _ab = sb + (buf) * 32768u; \
        uint32_t _bb = _ab + 16384u; \
        _Pragma("unroll") \
        for (int _j = 0; _j < 4; _j++) { \
            int _row = r0 + 32 * _j; \
            const __nv_bfloat16* _sa = _Ap + (size_t)(rowBase + _row) * KDIM + _c * 64 + seg * 8; \
            CP_ASYNC16(_ab + swz128(_row * 128 + seg * 16), _sa); \
            const __nv_bfloat16* _sbp = _Bp + (size_t)(colBase + _row) * KDIM + _c * 64 + seg * 8; \
            CP_ASYNC16(_bb + swz128(_row * 128 + seg * 16), _sbp); \
        } \
        CP_COMMIT(); \
    } while (0)

    LOAD_CHUNK(0, 0);

    for (int ch = 0; ch < 12; ch++) {
        int buf = ch & 1;
        if (ch < 11) { LOAD_CHUNK(ch + 1, buf ^ 1); CP_WAIT1(); }
        else CP_WAIT0();
        __syncthreads();

        uint32_t abase = sb + buf * 32768u;
        uint32_t bbase = abase + 16384u;
#pragma unroll
        for (int kk = 0; kk < 4; kk++) {
            uint32_t afr[2][4];
#pragma unroll
            for (int mt = 0; mt < 2; mt++) {
                int row = warpm * 32 + mt * 16 + (lane & 15);
                int colb = kk * 32 + ((lane >> 4) << 4);
                LDMATRIX_X4(afr[mt][0], afr[mt][1], afr[mt][2], afr[mt][3],
                            abase + swz128(row * 128 + colb));
            }
            uint32_t bfr[8][2];
#pragma unroll
            for (int pb = 0; pb < 4; pb++) {
                int n = warpn * 64 + pb * 16 + ((lane >> 4) << 3) + (lane & 7);
                int colb = kk * 32 + (((lane >> 3) & 1) << 4);
                uint32_t t0, t1, t2, t3;
                LDMATRIX_X4(t0, t1, t2, t3, bbase + swz128(n * 128 + colb));
                bfr[2 * pb][0] = t0; bfr[2 * pb][1] = t1;
                bfr[2 * pb + 1][0] = t2; bfr[2 * pb + 1][1] = t3;
            }
#pragma unroll
            for (int mt = 0; mt < 2; mt++)
#pragma unroll
                for (int nt = 0; nt < 8; nt++)
                    MMA_BF16(acc[mt][nt], afr[mt], bfr[nt]);
        }
        __syncthreads();
    }

    // ---- epilogue ----
#pragma unroll
    for (int nt = 0; nt < 8; nt++) {
        int c = colBase + warpn * 64 + nt * 8 + 2 * (lane & 3);
        float b0 = __ldg(&bias[c]);
        float b1 = __ldg(&bias[c + 1]);
#pragma unroll
        for (int mt = 0; mt < 2; mt++) {
            acc[mt][nt][0] += b0; acc[mt][nt][1] += b1;
            acc[mt][nt][2] += b0; acc[mt][nt][3] += b1;
        }
    }

    if (mode == 1) {
#pragma unroll
        for (int mt = 0; mt < 2; mt++)
#pragma unroll
            for (int h = 0; h < 2; h++) {
                int row = rowBase + warpm * 32 + mt * 16 + h * 8 + (lane >> 2);
                float4 rp4 = __ldg((const float4*)rp + row);
                float rparr[4] = {rp4.x, rp4.y, rp4.z, rp4.w};
#pragma unroll
                for (int nt = 0; nt < 8; nt++) {
                    int l = (((warpn * 64 + nt * 8 + 2 * (lane & 3))) >> 2) & 3;
                    float invlen = __uint_as_float((uint32_t)(116 + l) << 23);
                    acc[mt][nt][2 * h]     = rparr[l] + acc[mt][nt][2 * h] * invlen;
                    acc[mt][nt][2 * h + 1] = rparr[l] + acc[mt][nt][2 * h + 1] * invlen;
                }
            }
    } else if (mode == 2) {
#pragma unroll
        for (int mt = 0; mt < 2; mt++)
#pragma unroll
            for (int h = 0; h < 2; h++)
#pragma unroll
                for (int g = 0; g < 4; g++) {
                    float v0 = acc[mt][2 * g][2 * h], v1 = acc[mt][2 * g][2 * h + 1];
                    float v2 = acc[mt][2 * g + 1][2 * h], v3 = acc[mt][2 * g + 1][2 * h + 1];
                    float mx = fmaxf(fmaxf(v0, v1), fmaxf(v2, v3));
                    mx = fmaxf(mx, __shfl_xor_sync(0xffffffffu, mx, 1));
                    mx = fmaxf(mx, __shfl_xor_sync(0xffffffffu, mx, 2));
                    v0 = expf(v0 - mx); v1 = expf(v1 - mx);
                    v2 = expf(v2 - mx); v3 = expf(v3 - mx);
                    float s = v0 + v1 + v2 + v3;
                    s += __shfl_xor_sync(0xffffffffu, s, 1);
                    s += __shfl_xor_sync(0xffffffffu, s, 2);
                    float inv = 1.0f / s;
                    acc[mt][2 * g][2 * h] = v0 * inv; acc[mt][2 * g][2 * h + 1] = v1 * inv;
                    acc[mt][2 * g + 1][2 * h] = v2 * inv; acc[mt][2 * g + 1][2 * h + 1] = v3 * inv;
                }
    }

#pragma unroll
    for (int mt = 0; mt < 2; mt++)
#pragma unroll
        for (int h = 0; h < 2; h++) {
            int row = rowBase + warpm * 32 + mt * 16 + h * 8 + (lane >> 2);
#pragma unroll
            for (int nt = 0; nt < 8; nt++) {
                int col = colBase + warpn * 64 + nt * 8 + 2 * (lane & 3);
                float2 o = {acc[mt][nt][2 * h], acc[mt][nt][2 * h + 1]};
                *(float2*)(out + (size_t)row * Ndim + col) = o;
            }
        }
}

// ---------------- deform: one warp per (n,q,m), lane = dh ----------------
__global__ void __launch_bounds__(256) deform_kernel(
    const float* __restrict__ d_loc, const float* __restrict__ d_attn)
{
    int gtid = blockIdx.x * blockDim.x + threadIdx.x;
    int warp = gtid >> 5;
    int lane = gtid & 31;
    if (warp >= NB * LQ * MM) return;

    int m = warp % MM;
    int nq = warp / MM;
    int n = nq / LQ;

    float v = (lane < 16) ? d_loc[(size_t)warp * LP + lane]
                          : d_attn[(size_t)warp * LP + (lane - 16)];

    const int leni[LL] = {2048, 1024, 512, 256};
    const float lenf[LL] = {2048.f, 1024.f, 512.f, 256.f};
    const int starti[LL] = {0, 2048, 3072, 3584};

    float acc = 0.f;
#pragma unroll
    for (int i = 0; i < LP; i++) {
        float loc = __shfl_sync(0xffffffffu, v, i);
        float aw = __shfl_sync(0xffffffffu, v, i + 16);
        int l = i >> 2;
        int Ti = leni[l];
        float pos = loc * lenf[l] - 0.5f;
        float x0f = floorf(pos);
        float frac = pos - x0f;
        int x0 = (int)x0f;
        float w0 = (x0 >= 0 && x0 < Ti) ? (1.0f - frac) : 0.0f;
        float w1 = (x0 + 1 >= 0 && x0 + 1 < Ti) ? frac : 0.0f;
        int i0 = min(max(x0, 0), Ti - 1);
        int i1 = min(max(x0 + 1, 0), Ti - 1);
        const float* base = g_value + ((size_t)(n * S_TOTAL + starti[l]) * MM + m) * DH + lane;
        float v0 = base[(size_t)i0 * MM * DH];
        float v1 = base[(size_t)i1 * MM * DH];
        acc += aw * (w0 * v0 + w1 * v1);
    }
    g_mixed[(size_t)nq * CC + m * DH + lane] = acc;
}

// ---------------- launch ----------------
extern "C" void kernel_launch(void* const* d_in, const int* in_sizes, int n_in,
                              void* d_out, int out_size)
{
    const float* query  = (const float*)d_in[0];
    const float* rp     = (const float*)d_in[1];
    const float* inp    = (const float*)d_in[2];
    const float* W_off  = (const float*)d_in[5];
    const float* b_off  = (const float*)d_in[6];
    const float* W_attn = (const float*)d_in[7];
    const float* b_attn = (const float*)d_in[8];
    const float* W_val  = (const float*)d_in[9];
    const float* b_val  = (const float*)d_in[10];
    const float* W_out  = (const float*)d_in[11];
    const float* b_out  = (const float*)d_in[12];

    float* out    = (float*)d_out;
    float* o_loc  = out + (size_t)NB * LQ * CC;
    float* o_attn = o_loc + (size_t)NB * LQ * MLP;

    cudaFuncSetAttribute(gemm_hmma_kernel, cudaFuncAttributeMaxDynamicSharedMemorySize, 65536);

    float *value, *mixed;
    __nv_bfloat16 *ih, *il, *qh, *ql, *mh, *ml;
    __nv_bfloat16 *wvh, *wvl, *woh, *wol, *wah, *wal, *wuh, *wul;
    cudaGetSymbolAddress((void**)&value, g_value);
    cudaGetSymbolAddress((void**)&mixed, g_mixed);
    cudaGetSymbolAddress((void**)&ih, g_inp_hi);  cudaGetSymbolAddress((void**)&il, g_inp_lo);
    cudaGetSymbolAddress((void**)&qh, g_q_hi);    cudaGetSymbolAddress((void**)&ql, g_q_lo);
    cudaGetSymbolAddress((void**)&mh, g_mx_hi);   cudaGetSymbolAddress((void**)&ml, g_mx_lo);
    cudaGetSymbolAddress((void**)&wvh, g_wv_hi);  cudaGetSymbolAddress((void**)&wvl, g_wv_lo);
    cudaGetSymbolAddress((void**)&woh, g_wo_hi);  cudaGetSymbolAddress((void**)&wol, g_wo_lo);
    cudaGetSymbolAddress((void**)&wah, g_wa_hi);  cudaGetSymbolAddress((void**)&wal, g_wa_lo);
    cudaGetSymbolAddress((void**)&wuh, g_wu_hi);  cudaGetSymbolAddress((void**)&wul, g_wu_lo);

    prep_weights_kernel<<<(2 * CC * KDIM + 2 * MLP * KDIM + 255) / 256, 256>>>(W_val, W_off, W_attn, W_out);
    split_kernel<<<(NB * S_TOTAL * CC / 4 + 255) / 256, 256>>>(inp, ih, il, NB * S_TOTAL * CC / 4);
    split_kernel<<<(NB * LQ * CC / 4 + 255) / 256, 256>>>(query, qh, ql, NB * LQ * CC / 4);

    // value projection (30720 x 256) @ (256 x 256)
    gemm_hmma_kernel<<<dim3(NB * S_TOTAL / 128, CC / 128), 256, 65536>>>(ih, il, wvh, wvl, b_val, value, CC, 0, nullptr);
    // loc: off GEMM + reference-point epilogue (16384 x 128)
    gemm_hmma_kernel<<<dim3(NB * LQ / 128, MLP / 128), 256, 65536>>>(qh, ql, woh, wol, b_off, o_loc, MLP, 1, rp);
    // attn: logits GEMM + softmax epilogue
    gemm_hmma_kernel<<<dim3(NB * LQ / 128, MLP / 128), 256, 65536>>>(qh, ql, wah, wal, b_attn, o_attn, MLP, 2, nullptr);

    // deformable sampling
    deform_kernel<<<(NB * LQ * MM * 32) / 256, 256>>>(o_loc, o_attn);

    // output projection
    split_kernel<<<(NB * LQ * CC / 4 + 255) / 256, 256>>>(mixed, mh, ml, NB * LQ * CC / 4);
    gemm_hmma_kernel<<<dim3(NB * LQ / 128, CC / 128), 256, 65536>>>(mh, ml, wuh, wul, b_out, out, CC, 0, nullptr);
}

// round 7
// speedup vs baseline: 2.1551x; 1.1321x over previous
#include <cuda_runtime.h>
#include <cuda_bf16.h>
#include <math.h>
#include <stdint.h>

#define NB 8
#define LQ 2048
#define CC 256
#define MM 8
#define LL 4
#define PP 4
#define DH 32
#define S_TOTAL 3840
#define MLP 128
#define LP 16
#define KDIM 256

// ---------------- scratch (no allocs allowed) ----------------
__device__ __align__(16) float g_value[NB * S_TOTAL * CC];
__device__ __align__(16) __nv_bfloat16 g_inp_hi[NB * S_TOTAL * CC];
__device__ __align__(16) __nv_bfloat16 g_inp_lo[NB * S_TOTAL * CC];
__device__ __align__(16) __nv_bfloat16 g_q_hi[NB * LQ * CC];
__device__ __align__(16) __nv_bfloat16 g_q_lo[NB * LQ * CC];
__device__ __align__(16) __nv_bfloat16 g_mx_hi[NB * LQ * CC];
__device__ __align__(16) __nv_bfloat16 g_mx_lo[NB * LQ * CC];
__device__ __align__(16) __nv_bfloat16 g_wv_hi[CC * KDIM], g_wv_lo[CC * KDIM];
__device__ __align__(16) __nv_bfloat16 g_wo_hi[MLP * KDIM], g_wo_lo[MLP * KDIM];
__device__ __align__(16) __nv_bfloat16 g_wa_hi[MLP * KDIM], g_wa_lo[MLP * KDIM];
__device__ __align__(16) __nv_bfloat16 g_wu_hi[CC * KDIM], g_wu_lo[CC * KDIM];

// ---------------- helpers ----------------
__device__ __forceinline__ uint32_t smem_u32(const void* p) {
    uint32_t a;
    asm("{ .reg .u64 t; cvta.to.shared.u64 t, %1; cvt.u32.u64 %0, t; }" : "=r"(a) : "l"(p));
    return a;
}
static __device__ __forceinline__ uint32_t swz128(uint32_t off) { return off ^ ((off >> 3) & 0x70); }

#define CP_ASYNC16(dst, src) \
    asm volatile("cp.async.cg.shared.global [%0], [%1], 16;" :: "r"(dst), "l"(src))
#define CP_COMMIT() asm volatile("cp.async.commit_group;" ::: "memory")
#define CP_WAIT1() asm volatile("cp.async.wait_group 1;" ::: "memory")
#define CP_WAIT0() asm volatile("cp.async.wait_group 0;" ::: "memory")

#define LDMATRIX_X4(r0, r1, r2, r3, addr) \
    asm volatile("ldmatrix.sync.aligned.m8n8.x4.shared.b16 {%0,%1,%2,%3}, [%4];" \
        : "=r"(r0), "=r"(r1), "=r"(r2), "=r"(r3) : "r"(addr))

#define MMA_BF16(c, a, b) \
    asm volatile("mma.sync.aligned.m16n8k16.row.col.f32.bf16.bf16.f32 " \
        "{%0,%1,%2,%3}, {%4,%5,%6,%7}, {%8,%9}, {%0,%1,%2,%3};" \
        : "+f"((c)[0]), "+f"((c)[1]), "+f"((c)[2]), "+f"((c)[3]) \
        : "r"((a)[0]), "r"((a)[1]), "r"((a)[2]), "r"((a)[3]), "r"((b)[0]), "r"((b)[1]))

// ---------------- weight transpose + split (W[k,n] -> Wt_hi/lo[n,k]) ----------------
__global__ void prep_weights_kernel(
    const float* __restrict__ Wv, const float* __restrict__ Wo,
    const float* __restrict__ Wa, const float* __restrict__ Wu)
{
    int i = blockIdx.x * blockDim.x + threadIdx.x;
    if (i >= 2 * CC * KDIM + 2 * MLP * KDIM) return;
    const float* W; __nv_bfloat16 *H, *Lo; int Nw, j;
    if (i < CC * KDIM)                       { W = Wv; H = g_wv_hi; Lo = g_wv_lo; Nw = CC;  j = i; }
    else if (i < CC * KDIM + MLP * KDIM)     { W = Wo; H = g_wo_hi; Lo = g_wo_lo; Nw = MLP; j = i - CC * KDIM; }
    else if (i < CC * KDIM + 2 * MLP * KDIM) { W = Wa; H = g_wa_hi; Lo = g_wa_lo; Nw = MLP; j = i - CC * KDIM - MLP * KDIM; }
    else                                     { W = Wu; H = g_wu_hi; Lo = g_wu_lo; Nw = CC;  j = i - CC * KDIM - 2 * MLP * KDIM; }
    int k = j & (KDIM - 1);
    int n = j >> 8;
    float x = W[k * Nw + n];
    __nv_bfloat16 h = __float2bfloat16(x);
    H[j] = h;
    Lo[j] = __float2bfloat16(x - __bfloat162float(h));
}

// ---------------- activation split fp32 -> hi/lo bf16 ----------------
__global__ void __launch_bounds__(256) split_kernel(
    const float* __restrict__ x, __nv_bfloat16* __restrict__ hi,
    __nv_bfloat16* __restrict__ lo, int n4)
{
    int i = blockIdx.x * blockDim.x + threadIdx.x;
    if (i >= n4) return;
    float4 v = ((const float4*)x)[i];
    float f[4] = {v.x, v.y, v.z, v.w};
    __nv_bfloat16 h[4], l[4];
#pragma unroll
    for (int t = 0; t < 4; t++) {
        h[t] = __float2bfloat16(f[t]);
        l[t] = __float2bfloat16(f[t] - __bfloat162float(h[t]));
    }
    ((__nv_bfloat162*)hi)[2 * i]     = __nv_bfloat162(h[0], h[1]);
    ((__nv_bfloat162*)hi)[2 * i + 1] = __nv_bfloat162(h[2], h[3]);
    ((__nv_bfloat162*)lo)[2 * i]     = __nv_bfloat162(l[0], l[1]);
    ((__nv_bfloat162*)lo)[2 * i + 1] = __nv_bfloat162(l[2], l[3]);
}

// ---------------- HMMA GEMM, shared-tile 3-pass: AhBh + AhBl + AlBh ----------------
// BM=128 BN=128 BK=64 slabs; per slab load {Ah, Al, Bh, Bl} once, run 3 passes.
// 2-stage pipeline, 128KB smem, 1 CTA/SM, 8 warps (4m x 2n), 64 acc/thread.
// modes: 0 = bias; 1 = loc epilogue (rp + v*invlen); 2 = softmax over 16-col groups
__global__ void __launch_bounds__(256) gemm_hmma_kernel(
    const __nv_bfloat16* __restrict__ Ahi, const __nv_bfloat16* __restrict__ Alo,
    const __nv_bfloat16* __restrict__ Bhi, const __nv_bfloat16* __restrict__ Blo,
    const float* __restrict__ bias, float* __restrict__ out,
    int Ndim, int mode, const float* __restrict__ rp)
{
    extern __shared__ char smem[];
    uint32_t sb = smem_u32(smem);
    const int tid = threadIdx.x;
    const int lane = tid & 31;
    const int wid = tid >> 5;
    const int warpm = wid & 3;     // 4 warps over M: 32 rows each
    const int warpn = wid >> 2;    // 2 warps over N: 64 cols each
    const int rowBase = blockIdx.x * 128;
    const int colBase = blockIdx.y * 128;

    const int seg = tid & 7;
    const int r0 = tid >> 3;       // 0..31

    float acc[2][8][4];
#pragma unroll
    for (int a = 0; a < 2; a++)
#pragma unroll
        for (int b = 0; b < 8; b++)
#pragma unroll
            for (int c = 0; c < 4; c++) acc[a][b][c] = 0.f;

    // stage buffer: Ah @0, Al @16K, Bh @32K, Bl @48K (each 128 rows x 128B)
#define LOAD_SLAB(c, stage) do { \
        uint32_t _base = sb + (stage) * 65536u; \
        _Pragma("unroll") \
        for (int _j = 0; _j < 4; _j++) { \
            int _row = r0 + 32 * _j; \
            uint32_t _sw = swz128(_row * 128 + seg * 16); \
            size_t _ga = (size_t)(rowBase + _row) * KDIM + (c) * 64 + seg * 8; \
            size_t _gb = (size_t)(colBase + _row) * KDIM + (c) * 64 + seg * 8; \
            CP_ASYNC16(_base + _sw,          Ahi + _ga); \
            CP_ASYNC16(_base + 16384u + _sw, Alo + _ga); \
            CP_ASYNC16(_base + 32768u + _sw, Bhi + _gb); \
            CP_ASYNC16(_base + 49152u + _sw, Blo + _gb); \
        } \
        CP_COMMIT(); \
    } while (0)

    LOAD_SLAB(0, 0);

    for (int c = 0; c < 4; c++) {
        int stage = c & 1;
        if (c < 3) { LOAD_SLAB(c + 1, stage ^ 1); CP_WAIT1(); }
        else CP_WAIT0();
        __syncthreads();

        uint32_t base = sb + stage * 65536u;
#pragma unroll
        for (int kk = 0; kk < 4; kk++) {
            uint32_t ah[2][4], al[2][4];
#pragma unroll
            for (int mt = 0; mt < 2; mt++) {
                uint32_t aoff = swz128((warpm * 32 + mt * 16 + (lane & 15)) * 128
                                       + kk * 32 + ((lane >> 4) << 4));
                LDMATRIX_X4(ah[mt][0], ah[mt][1], ah[mt][2], ah[mt][3], base + aoff);
                LDMATRIX_X4(al[mt][0], al[mt][1], al[mt][2], al[mt][3], base + 16384u + aoff);
            }
            uint32_t bh[8][2], bl[8][2];
#pragma unroll
            for (int pb = 0; pb < 4; pb++) {
                uint32_t boff = swz128((warpn * 64 + pb * 16 + ((lane >> 4) << 3) + (lane & 7)) * 128
                                       + kk * 32 + (((lane >> 3) & 1) << 4));
                uint32_t t0, t1, t2, t3;
                LDMATRIX_X4(t0, t1, t2, t3, base + 32768u + boff);
                bh[2 * pb][0] = t0; bh[2 * pb][1] = t1;
                bh[2 * pb + 1][0] = t2; bh[2 * pb + 1][1] = t3;
                LDMATRIX_X4(t0, t1, t2, t3, base + 49152u + boff);
                bl[2 * pb][0] = t0; bl[2 * pb][1] = t1;
                bl[2 * pb + 1][0] = t2; bl[2 * pb + 1][1] = t3;
            }
#pragma unroll
            for (int mt = 0; mt < 2; mt++)
#pragma unroll
                for (int nt = 0; nt < 8; nt++)
                    MMA_BF16(acc[mt][nt], ah[mt], bh[nt]);
#pragma unroll
            for (int mt = 0; mt < 2; mt++)
#pragma unroll
                for (int nt = 0; nt < 8; nt++)
                    MMA_BF16(acc[mt][nt], ah[mt], bl[nt]);
#pragma unroll
            for (int mt = 0; mt < 2; mt++)
#pragma unroll
                for (int nt = 0; nt < 8; nt++)
                    MMA_BF16(acc[mt][nt], al[mt], bh[nt]);
        }
        __syncthreads();
    }

    // ---- epilogue ----
#pragma unroll
    for (int nt = 0; nt < 8; nt++) {
        int c = colBase + warpn * 64 + nt * 8 + 2 * (lane & 3);
        float b0 = __ldg(&bias[c]);
        float b1 = __ldg(&bias[c + 1]);
#pragma unroll
        for (int mt = 0; mt < 2; mt++) {
            acc[mt][nt][0] += b0; acc[mt][nt][1] += b1;
            acc[mt][nt][2] += b0; acc[mt][nt][3] += b1;
        }
    }

    if (mode == 1) {
#pragma unroll
        for (int mt = 0; mt < 2; mt++)
#pragma unroll
            for (int h = 0; h < 2; h++) {
                int row = rowBase + warpm * 32 + mt * 16 + h * 8 + (lane >> 2);
                float4 rp4 = __ldg((const float4*)rp + row);
                float rparr[4] = {rp4.x, rp4.y, rp4.z, rp4.w};
#pragma unroll
                for (int nt = 0; nt < 8; nt++) {
                    int l = (((warpn * 64 + nt * 8 + 2 * (lane & 3))) >> 2) & 3;
                    float invlen = __uint_as_float((uint32_t)(116 + l) << 23);
                    acc[mt][nt][2 * h]     = rparr[l] + acc[mt][nt][2 * h] * invlen;
                    acc[mt][nt][2 * h + 1] = rparr[l] + acc[mt][nt][2 * h + 1] * invlen;
                }
            }
    } else if (mode == 2) {
#pragma unroll
        for (int mt = 0; mt < 2; mt++)
#pragma unroll
            for (int h = 0; h < 2; h++)
#pragma unroll
                for (int g = 0; g < 4; g++) {
                    float v0 = acc[mt][2 * g][2 * h], v1 = acc[mt][2 * g][2 * h + 1];
                    float v2 = acc[mt][2 * g + 1][2 * h], v3 = acc[mt][2 * g + 1][2 * h + 1];
                    float mx = fmaxf(fmaxf(v0, v1), fmaxf(v2, v3));
                    mx = fmaxf(mx, __shfl_xor_sync(0xffffffffu, mx, 1));
                    mx = fmaxf(mx, __shfl_xor_sync(0xffffffffu, mx, 2));
                    v0 = expf(v0 - mx); v1 = expf(v1 - mx);
                    v2 = expf(v2 - mx); v3 = expf(v3 - mx);
                    float s = v0 + v1 + v2 + v3;
                    s += __shfl_xor_sync(0xffffffffu, s, 1);
                    s += __shfl_xor_sync(0xffffffffu, s, 2);
                    float inv = 1.0f / s;
                    acc[mt][2 * g][2 * h] = v0 * inv; acc[mt][2 * g][2 * h + 1] = v1 * inv;
                    acc[mt][2 * g + 1][2 * h] = v2 * inv; acc[mt][2 * g + 1][2 * h + 1] = v3 * inv;
                }
    }

#pragma unroll
    for (int mt = 0; mt < 2; mt++)
#pragma unroll
        for (int h = 0; h < 2; h++) {
            int row = rowBase + warpm * 32 + mt * 16 + h * 8 + (lane >> 2);
#pragma unroll
            for (int nt = 0; nt < 8; nt++) {
                int col = colBase + warpn * 64 + nt * 8 + 2 * (lane & 3);
                float2 o = {acc[mt][nt][2 * h], acc[mt][nt][2 * h + 1]};
                *(float2*)(out + (size_t)row * Ndim + col) = o;
            }
        }
}

// ---------------- deform: one warp per (n,q,m), lane = dh; writes bf16 hi/lo ----------------
__global__ void __launch_bounds__(256) deform_kernel(
    const float* __restrict__ d_loc, const float* __restrict__ d_attn)
{
    int gtid = blockIdx.x * blockDim.x + threadIdx.x;
    int warp = gtid >> 5;
    int lane = gtid & 31;
    if (warp >= NB * LQ * MM) return;

    int m = warp % MM;
    int nq = warp / MM;
    int n = nq / LQ;

    float v = (lane < 16) ? d_loc[(size_t)warp * LP + lane]
                          : d_attn[(size_t)warp * LP + (lane - 16)];

    const int leni[LL] = {2048, 1024, 512, 256};
    const float lenf[LL] = {2048.f, 1024.f, 512.f, 256.f};
    const int starti[LL] = {0, 2048, 3072, 3584};

    float acc = 0.f;
#pragma unroll
    for (int i = 0; i < LP; i++) {
        float loc = __shfl_sync(0xffffffffu, v, i);
        float aw = __shfl_sync(0xffffffffu, v, i + 16);
        int l = i >> 2;
        int Ti = leni[l];
        float pos = loc * lenf[l] - 0.5f;
        float x0f = floorf(pos);
        float frac = pos - x0f;
        int x0 = (int)x0f;
        float w0 = (x0 >= 0 && x0 < Ti) ? (1.0f - frac) : 0.0f;
        float w1 = (x0 + 1 >= 0 && x0 + 1 < Ti) ? frac : 0.0f;
        int i0 = min(max(x0, 0), Ti - 1);
        int i1 = min(max(x0 + 1, 0), Ti - 1);
        const float* base = g_value + ((size_t)(n * S_TOTAL + starti[l]) * MM + m) * DH + lane;
        float v0 = base[(size_t)i0 * MM * DH];
        float v1 = base[(size_t)i1 * MM * DH];
        acc += aw * (w0 * v0 + w1 * v1);
    }
    size_t oi = (size_t)nq * CC + m * DH + lane;
    __nv_bfloat16 h = __float2bfloat16(acc);
    g_mx_hi[oi] = h;
    g_mx_lo[oi] = __float2bfloat16(acc - __bfloat162float(h));
}

// ---------------- launch ----------------
extern "C" void kernel_launch(void* const* d_in, const int* in_sizes, int n_in,
                              void* d_out, int out_size)
{
    const float* query  = (const float*)d_in[0];
    const float* rp     = (const float*)d_in[1];
    const float* inp    = (const float*)d_in[2];
    const float* W_off  = (const float*)d_in[5];
    const float* b_off  = (const float*)d_in[6];
    const float* W_attn = (const float*)d_in[7];
    const float* b_attn = (const float*)d_in[8];
    const float* W_val  = (const float*)d_in[9];
    const float* b_val  = (const float*)d_in[10];
    const float* W_out  = (const float*)d_in[11];
    const float* b_out  = (const float*)d_in[12];

    float* out    = (float*)d_out;
    float* o_loc  = out + (size_t)NB * LQ * CC;
    float* o_attn = o_loc + (size_t)NB * LQ * MLP;

    cudaFuncSetAttribute(gemm_hmma_kernel, cudaFuncAttributeMaxDynamicSharedMemorySize, 131072);

    float* value;
    __nv_bfloat16 *ih, *il, *qh, *ql, *mh, *ml;
    __nv_bfloat16 *wvh, *wvl, *woh, *wol, *wah, *wal, *wuh, *wul;
    cudaGetSymbolAddress((void**)&value, g_value);
    cudaGetSymbolAddress((void**)&ih, g_inp_hi);  cudaGetSymbolAddress((void**)&il, g_inp_lo);
    cudaGetSymbolAddress((void**)&qh, g_q_hi);    cudaGetSymbolAddress((void**)&ql, g_q_lo);
    cudaGetSymbolAddress((void**)&mh, g_mx_hi);   cudaGetSymbolAddress((void**)&ml, g_mx_lo);
    cudaGetSymbolAddress((void**)&wvh, g_wv_hi);  cudaGetSymbolAddress((void**)&wvl, g_wv_lo);
    cudaGetSymbolAddress((void**)&woh, g_wo_hi);  cudaGetSymbolAddress((void**)&wol, g_wo_lo);
    cudaGetSymbolAddress((void**)&wah, g_wa_hi);  cudaGetSymbolAddress((void**)&wal, g_wa_lo);
    cudaGetSymbolAddress((void**)&wuh, g_wu_hi);  cudaGetSymbolAddress((void**)&wul, g_wu_lo);

    // fork/join streams (created fresh each call; capturable fork via events)
    cudaStream_t s2;
    cudaStreamCreateWithFlags(&s2, cudaStreamNonBlocking);
    cudaEvent_t e1, e2;
    cudaEventCreateWithFlags(&e1, cudaEventDisableTiming);
    cudaEventCreateWithFlags(&e2, cudaEventDisableTiming);

    // main stream: weight prep -> inp split -> value GEMM
    prep_weights_kernel<<<(2 * CC * KDIM + 2 * MLP * KDIM + 255) / 256, 256>>>(W_val, W_off, W_attn, W_out);
    cudaEventRecord(e1, 0);
    cudaStreamWaitEvent(s2, e1, 0);

    // side stream: q split -> loc GEMM -> attn GEMM
    split_kernel<<<(NB * LQ * CC / 4 + 255) / 256, 256, 0, s2>>>(query, qh, ql, NB * LQ * CC / 4);
    gemm_hmma_kernel<<<dim3(NB * LQ / 128, 1), 256, 131072, s2>>>(qh, ql, woh, wol, b_off, o_loc, MLP, 1, rp);
    gemm_hmma_kernel<<<dim3(NB * LQ / 128, 1), 256, 131072, s2>>>(qh, ql, wah, wal, b_attn, o_attn, MLP, 2, nullptr);
    cudaEventRecord(e2, s2);

    // main stream (concurrent with side): inp split + value GEMM
    split_kernel<<<(NB * S_TOTAL * CC / 4 + 255) / 256, 256>>>(inp, ih, il, NB * S_TOTAL * CC / 4);
    gemm_hmma_kernel<<<dim3(NB * S_TOTAL / 128, CC / 128), 256, 131072>>>(ih, il, wvh, wvl, b_val, value, CC, 0, nullptr);

    // join, then deform + output projection
    cudaStreamWaitEvent(0, e2, 0);
    deform_kernel<<<(NB * LQ * MM * 32) / 256, 256>>>(o_loc, o_attn);
    gemm_hmma_kernel<<<dim3(NB * LQ / 128, CC / 128), 256, 131072>>>(mh, ml, wuh, wul, b_out, out, CC, 0, nullptr);
    // streams/events intentionally not destroyed during capture (few calls; host-side only)
}